// round 16
// baseline (speedup 1.0000x reference)
#include <cuda_runtime.h>
#include <stdint.h>

// Problem constants (fixed by the dataset)
#define NPTS      32768
#define NKERN     4
#define GRID      16
#define C_IN      64
#define C_OUT     64
#define NCELLS    (NKERN * GRID * GRID * GRID)   // 16384
#define NENT      (NPTS * 8)                     // 262144
#define CPC       8                              // cells per CTA
#define NGEMM     (NCELLS / CPC)                 // 2048 CTAs
#define B         32                             // batch (slots)
#define YROW      68                             // floats per y row (272B, 16B-aligned)
#define NTHR      128                            // 4 warps
#define MAXPER    128                            // bucket capacity (mean 16, P(>128)<1e-20)

// ---------------------------------------------------------------------------
// Device scratch (static __device__ globals; no cudaMalloc anywhere).
// g_counts zero at load; re-zeroed by k_cell_gemm each call (each CTA owns
// its CPC cells exclusively).  Bucket slots beyond count hold stale-but-
// valid entry ids (zero on first call); all consumers guard with slot<nb.
// ---------------------------------------------------------------------------
__device__ unsigned g_counts[NCELLS];
__device__ unsigned g_sorted[(size_t)NCELLS * MAXPER];   // 8MB
__device__ float    g_swts[(size_t)NCELLS * MAXPER];     // 8MB

// ---------------------------------------------------------------------------
// asm helpers
// ---------------------------------------------------------------------------
__device__ __forceinline__ void ffma2(unsigned long long& d,
                                      unsigned long long a,
                                      unsigned long long b) {
    asm("fma.rn.f32x2 %0, %1, %2, %0;" : "+l"(d) : "l"(a), "l"(b));
}
__device__ __forceinline__ unsigned long long bcast2(float v) {
    unsigned long long r;
    asm("mov.b64 %0, {%1, %1};" : "=l"(r) : "f"(v));
    return r;
}
__device__ __forceinline__ float2 unpack2(unsigned long long v) {
    float2 r;
    asm("mov.b64 {%0, %1}, %2;" : "=f"(r.x), "=f"(r.y) : "l"(v));
    return r;
}
__device__ __forceinline__ uint32_t smem_u32(const void* p) {
    uint32_t a;
    asm("{ .reg .u64 t; cvta.to.shared.u64 t, %1; cvt.u32.u64 %0, t; }"
        : "=r"(a) : "l"(p));
    return a;
}
__device__ __forceinline__ void mbar_init(uint32_t mbar, unsigned count) {
    asm volatile("mbarrier.init.shared.b64 [%0], %1;" :: "r"(mbar), "r"(count) : "memory");
}
__device__ __forceinline__ void mbar_expect_tx(uint32_t mbar, unsigned bytes) {
    asm volatile("mbarrier.arrive.expect_tx.shared.b64 _, [%0], %1;"
                 :: "r"(mbar), "r"(bytes) : "memory");
}
__device__ __forceinline__ void mbar_wait(uint32_t mbar, unsigned parity) {
    asm volatile(
        "{\n\t.reg .pred P;\n"
        "W%=:\n\t"
        "mbarrier.try_wait.parity.shared::cta.b64 P, [%0], %1, 0x989680;\n\t"
        "@P bra D%=;\n\t"
        "bra W%=;\n"
        "D%=:\n\t}"
        :: "r"(mbar), "r"(parity) : "memory");
}
__device__ __forceinline__ void bulk_g2s(uint32_t dst, const void* src,
                                         unsigned bytes, uint32_t mbar) {
    asm volatile(
        "cp.async.bulk.shared::cta.global.mbarrier::complete_tx::bytes "
        "[%0], [%1], %2, [%3];"
        :: "r"(dst), "l"(src), "r"(bytes), "r"(mbar) : "memory");
}
__device__ __forceinline__ void red_add_v4(float* gptr, float4 v) {
    asm volatile("red.global.add.v4.f32 [%0], {%1, %2, %3, %4};"
                 :: "l"(gptr), "f"(v.x), "f"(v.y), "f"(v.z), "f"(v.w)
                 : "memory");
}
__device__ __forceinline__ void cp_async16(uint32_t dst, const void* src) {
    asm volatile("cp.async.cg.shared.global [%0], [%1], 16;"
                 :: "r"(dst), "l"(src) : "memory");
}
__device__ __forceinline__ void cp_async4(uint32_t dst, const void* src) {
    asm volatile("cp.async.ca.shared.global [%0], [%1], 4;"
                 :: "r"(dst), "l"(src) : "memory");
}
__device__ __forceinline__ void cp_commit() {
    asm volatile("cp.async.commit_group;" ::: "memory");
}
__device__ __forceinline__ void cp_wait1() {
    asm volatile("cp.async.wait_group 1;" ::: "memory");
}

// ---------------------------------------------------------------------------
// K1: zero d_out + per-point corners/weights appended DIRECTLY into
//     fixed-capacity cell buckets (replaces histogram+scan+scatter).
// ---------------------------------------------------------------------------
__global__ void k_prep(const int* __restrict__ pidx,
                       const float* __restrict__ pos,
                       float* __restrict__ out) {
    int n = blockIdx.x * blockDim.x + threadIdx.x;

    float4 z = make_float4(0.f, 0.f, 0.f, 0.f);
    #pragma unroll
    for (int i = n; i < NPTS * (C_OUT / 4); i += NPTS)
        ((float4*)out)[i] = z;

    if (n >= NPTS) return;

    float lx = pos[n * 3 + 0] * (float)GRID - 0.5f;
    float ly = pos[n * 3 + 1] * (float)GRID - 0.5f;
    float lz = pos[n * 3 + 2] * (float)GRID - 0.5f;
    float fx = floorf(lx), fy = floorf(ly), fz = floorf(lz);
    float cwx = lx - fx, cwy = ly - fy, cwz = lz - fz;
    float fwx = 1.f - cwx, fwy = 1.f - cwy, fwz = 1.f - cwz;
    int ix = (int)fx, iy = (int)fy, iz = (int)fz;
    int pi = pidx[n];

    #pragma unroll
    for (int k = 0; k < 8; k++) {
        int bx = k & 1, by = (k >> 1) & 1, bz = (k >> 2) & 1;
        int jx = min(max(ix + bx, 0), GRID - 1);
        int jy = min(max(iy + by, 0), GRID - 1);
        int jz = min(max(iz + bz, 0), GRID - 1);
        float w = (bx ? cwx : fwx) * (by ? cwy : fwy) * (bz ? cwz : fwz);
        unsigned cell = (((unsigned)pi * GRID + jz) * GRID + jy) * GRID + jx;
        unsigned slot = atomicAdd(&g_counts[cell], 1u);
        size_t idx = (size_t)cell * MAXPER + slot;
        g_sorted[idx] = (unsigned)(n * 8 + k);
        g_swts[idx] = w;
    }
}

// ---------------------------------------------------------------------------
// K2: pipelined per-cell GEMM (identical inner structure to the proven
//     141.8us kernel), reading fixed-capacity buckets.
//   - 128 thr, B=32.  fj = t&15 (16 col groups of 4), ei = t>>4 (8 slot
//     groups of 4).  Thread tile: 4 slots x 4 cols (0.125 LDS.128/MAC).
//   - Warp w covers slots [8w, 8w+8): whole-warp padding skip.
//   - y staged as raw xs rows via cp.async one batch ahead (w in epilogue);
//     e/w staged three batches ahead; wait_group 1.
//   - K (16KB)+bias double-buffered via cp.async.bulk + mbarrier.
//   - Epilogue: red.global.add.v4.f32 straight into d_out.
//   - Resets g_counts for its cells (next call's prep needs zeros).
// ---------------------------------------------------------------------------
#define KBYTES   (C_IN * C_OUT * 4)          // 16384
#define BBYTES   (C_OUT * 4)                 // 256
#define TXBYTES  (KBYTES + BBYTES)           // 16640

#define ADV(ci, bs) do { (bs) += B;                                           \
    while ((ci) < CPC && (bs) >= (int)scnt[(ci)]) { (ci)++; (bs) = 0; }       \
    } while (0)

__global__ __launch_bounds__(NTHR) void k_cell_gemm(
    const float* __restrict__ xs,
    const float* __restrict__ kernels,
    const float* __restrict__ biases,
    float* __restrict__ out) {

    __shared__ __align__(16) float ksm[2][C_IN * C_OUT];   // 32KB
    __shared__ __align__(16) float bsm[2][C_OUT];          // 512B
    __shared__ __align__(16) float ybuf[2][B][YROW];       // 17.4KB
    __shared__ unsigned ebuf[4][B];                        // 512B
    __shared__ float    wbuf[4][B];                        // 512B
    __shared__ int      scnt[CPC];
    __shared__ __align__(8) unsigned long long mbar_s[2];

    const int t  = threadIdx.x;      // 0..127
    const int fj = t & 15;           // 16 col groups of 4
    const int ei = t >> 4;           // 8 slot groups of 4
    const int yb = ei * 4;           // first of this thread's 4 slots
    const int kb = fj * 4;           // first of this thread's 4 columns
    const int cell0 = blockIdx.x * CPC;

    uint32_t mb0 = smem_u32(&mbar_s[0]);
    uint32_t mb1 = smem_u32(&mbar_s[1]);
    uint32_t kd0 = smem_u32(&ksm[0][0]);
    uint32_t kd1 = smem_u32(&ksm[1][0]);
    uint32_t bd0 = smem_u32(&bsm[0][0]);
    uint32_t bd1 = smem_u32(&bsm[1][0]);

    // load counts and reset them for the next call (CTA owns these cells)
    if (t < CPC) {
        unsigned c = g_counts[cell0 + t];
        scnt[t] = (int)c;
        g_counts[cell0 + t] = 0u;
    }
    if (t == 0) { mbar_init(mb0, 1); mbar_init(mb1, 1); }
    __syncthreads();

    // compute cursor (batch b)
    int cci = 0, cbase = 0;
    while (cci < CPC && scnt[cci] == 0) cci++;
    if (cci == CPC) return;   // empty CTA (counts already reset)

    // prologue: K for first nonempty cell into buf0
    if (t == 0) {
        mbar_expect_tx(mb0, TXBYTES);
        bulk_g2s(kd0, kernels + (size_t)(cell0 + cci) * (C_IN * C_OUT), KBYTES, mb0);
        bulk_g2s(bd0, biases  + (size_t)(cell0 + cci) * C_OUT,          BBYTES, mb0);
    }

    // cursor copies for batches 1..4
    int c1i = cci, c1b = cbase; ADV(c1i, c1b);
    int c2i = c1i, c2b = c1b;   ADV(c2i, c2b);
    int c3i = c2i, c3b = c2b;   ADV(c3i, c3b);
    int c4i = c3i, c4b = c3b;   ADV(c4i, c4b);

    // sync-load e/w for batches 0 and 1
    if (t < B) {
        size_t s0 = (size_t)(cell0 + cci) * MAXPER + cbase;
        ebuf[0][t] = g_sorted[s0 + t];
        wbuf[0][t] = g_swts[s0 + t];
        if (c1i < CPC) {
            size_t s1 = (size_t)(cell0 + c1i) * MAXPER + c1b;
            ebuf[1][t] = g_sorted[s1 + t];
            wbuf[1][t] = g_swts[s1 + t];
        }
    }
    __syncthreads();

    // group A: y[0] (from ebuf[0]) + e[2]   (512 x 16B over 128 threads)
    {
        #pragma unroll
        for (int k = 0; k < 4; k++) {
            int idx = t + k * NTHR, row = idx >> 4, ch = idx & 15;
            unsigned e = ebuf[0][row];
            cp_async16(smem_u32(&ybuf[0][row][0]) + ch * 16,
                       xs + (size_t)(e >> 3) * C_IN + ch * 4);
        }
        if (c2i < CPC) {
            size_t s2 = (size_t)(cell0 + c2i) * MAXPER + c2b;
            if (t < B)            cp_async4(smem_u32(&ebuf[2][t]),     g_sorted + s2 + t);
            else if (t < 2 * B)   cp_async4(smem_u32(&wbuf[2][t - B]), g_swts   + s2 + (t - B));
        }
        cp_commit();
    }
    // group B: y[1] (from ebuf[1]) + e[3]
    {
        if (c1i < CPC) {
            #pragma unroll
            for (int k = 0; k < 4; k++) {
                int idx = t + k * NTHR, row = idx >> 4, ch = idx & 15;
                unsigned e = ebuf[1][row];
                cp_async16(smem_u32(&ybuf[1][row][0]) + ch * 16,
                           xs + (size_t)(e >> 3) * C_IN + ch * 4);
            }
        }
        if (c3i < CPC) {
            size_t s3 = (size_t)(cell0 + c3i) * MAXPER + c3b;
            if (t < B)            cp_async4(smem_u32(&ebuf[3][t]),     g_sorted + s3 + t);
            else if (t < 2 * B)   cp_async4(smem_u32(&wbuf[3][t - B]), g_swts   + s3 + (t - B));
        }
        cp_commit();
    }
    cp_wait1();        // group A complete: y[0], e[2]
    __syncthreads();

    unsigned kpar0 = 0, kpar1 = 0;
    int kq = -1, prev_ci = -1;
    int b = 0;
    int ici = c2i, icb = c2b;   // issue cursor (batch b+2)
    int eci = c4i, ecb = c4b;   // e cursor (batch b+4)

    while (cci < CPC) {
        int nent = scnt[cci];
        int nb = min(B, nent - cbase);
        bool newcell = (cci != prev_ci);
        prev_ci = cci;

        if (newcell) {
            kq++;
            if (t == 0) {
                int nc = cci + 1;
                while (nc < CPC && scnt[nc] == 0) nc++;
                if (nc < CPC) {
                    int nbuf = (kq + 1) & 1;
                    uint32_t mb = nbuf ? mb1 : mb0;
                    mbar_expect_tx(mb, TXBYTES);
                    bulk_g2s(nbuf ? kd1 : kd0,
                             kernels + (size_t)(cell0 + nc) * (C_IN * C_OUT), KBYTES, mb);
                    bulk_g2s(nbuf ? bd1 : bd0,
                             biases + (size_t)(cell0 + nc) * C_OUT, BBYTES, mb);
                }
            }
            if (kq & 1) { mbar_wait(mb1, kpar1); kpar1 ^= 1u; }
            else        { mbar_wait(mb0, kpar0); kpar0 ^= 1u; }
        }

        const int kbuf = kq & 1;
        const int ysel = b & 1;
        const int ring = b & 3;

        // ---- compute batch b (warps whose 8 slots are all padding skip) ----
        if (yb < nb) {
            const float* kcur = ksm[kbuf];
            const float* bcur = bsm[kbuf];
            const float* y0p = &ybuf[ysel][yb + 0][0];
            const float* y1p = &ybuf[ysel][yb + 1][0];
            const float* y2p = &ybuf[ysel][yb + 2][0];
            const float* y3p = &ybuf[ysel][yb + 3][0];
            unsigned long long a0[2] = {0, 0}, a1[2] = {0, 0};
            unsigned long long a2[2] = {0, 0}, a3[2] = {0, 0};

            #pragma unroll
            for (int cb = 0; cb < 16; cb++) {
                float4 ya = *(const float4*)(y0p + cb * 4);
                float4 ybv = *(const float4*)(y1p + cb * 4);
                float4 yc = *(const float4*)(y2p + cb * 4);
                float4 yd = *(const float4*)(y3p + cb * 4);
                const float* kp = kcur + cb * 4 * C_OUT + kb;
                ulonglong2 k0 = *(const ulonglong2*)(kp);
                ulonglong2 k1 = *(const ulonglong2*)(kp + C_OUT);
                ulonglong2 k2 = *(const ulonglong2*)(kp + 2 * C_OUT);
                ulonglong2 k3 = *(const ulonglong2*)(kp + 3 * C_OUT);
                unsigned long long u;
                u = bcast2(ya.x);  ffma2(a0[0], u, k0.x); ffma2(a0[1], u, k0.y);
                u = bcast2(ya.y);  ffma2(a0[0], u, k1.x); ffma2(a0[1], u, k1.y);
                u = bcast2(ya.z);  ffma2(a0[0], u, k2.x); ffma2(a0[1], u, k2.y);
                u = bcast2(ya.w);  ffma2(a0[0], u, k3.x); ffma2(a0[1], u, k3.y);
                u = bcast2(ybv.x); ffma2(a1[0], u, k0.x); ffma2(a1[1], u, k0.y);
                u = bcast2(ybv.y); ffma2(a1[0], u, k1.x); ffma2(a1[1], u, k1.y);
                u = bcast2(ybv.z); ffma2(a1[0], u, k2.x); ffma2(a1[1], u, k2.y);
                u = bcast2(ybv.w); ffma2(a1[0], u, k3.x); ffma2(a1[1], u, k3.y);
                u = bcast2(yc.x);  ffma2(a2[0], u, k0.x); ffma2(a2[1], u, k0.y);
                u = bcast2(yc.y);  ffma2(a2[0], u, k1.x); ffma2(a2[1], u, k1.y);
                u = bcast2(yc.z);  ffma2(a2[0], u, k2.x); ffma2(a2[1], u, k2.y);
                u = bcast2(yc.w);  ffma2(a2[0], u, k3.x); ffma2(a2[1], u, k3.y);
                u = bcast2(yd.x);  ffma2(a3[0], u, k0.x); ffma2(a3[1], u, k0.y);
                u = bcast2(yd.y);  ffma2(a3[0], u, k1.x); ffma2(a3[1], u, k1.y);
                u = bcast2(yd.z);  ffma2(a3[0], u, k2.x); ffma2(a3[1], u, k2.y);
                u = bcast2(yd.w);  ffma2(a3[0], u, k3.x); ffma2(a3[1], u, k3.y);
            }

            float bx = bcur[kb],     by = bcur[kb + 1];
            float bz = bcur[kb + 2], bw = bcur[kb + 3];
            unsigned long long* accs[4] = {a0, a1, a2, a3};
            #pragma unroll
            for (int j = 0; j < 4; j++) {
                int slot = yb + j;
                if (slot < nb) {
                    unsigned e = ebuf[ring][slot];
                    float wt = wbuf[ring][slot];
                    float2 lo = unpack2(accs[j][0]);
                    float2 hi = unpack2(accs[j][1]);
                    float4 o = make_float4(wt * (lo.x + bx), wt * (lo.y + by),
                                           wt * (hi.x + bz), wt * (hi.y + bw));
                    red_add_v4(out + (size_t)(e >> 3) * C_OUT + kb, o);
                }
            }
        }
        __syncthreads();   // everyone done with ybuf[ysel], ebuf[ring]

        // ---- issue group b+2: y[b+2] into ybuf[ysel], e[b+4] into ring ----
        if (ici < CPC) {
            int iring = (b + 2) & 3;
            #pragma unroll
            for (int k = 0; k < 4; k++) {
                int idx = t + k * NTHR, row = idx >> 4, ch = idx & 15;
                unsigned e = ebuf[iring][row];
                cp_async16(smem_u32(&ybuf[ysel][row][0]) + ch * 16,
                           xs + (size_t)(e >> 3) * C_IN + ch * 4);
            }
        }
        if (eci < CPC) {
            int ering = (b + 4) & 3;   // == ring; e[b] is dead now
            size_t es = (size_t)(cell0 + eci) * MAXPER + ecb;
            if (t < B)          cp_async4(smem_u32(&ebuf[ering][t]),     g_sorted + es + t);
            else if (t < 2 * B) cp_async4(smem_u32(&wbuf[ering][t - B]), g_swts   + es + (t - B));
        }
        cp_commit();
        cp_wait1();        // group b+1 complete: y[b+1], e[b+3]
        __syncthreads();

        ADV(cci, cbase);
        ADV(ici, icb);
        ADV(eci, ecb);
        b++;
    }
}

// ---------------------------------------------------------------------------
// Launcher (graph-capturable).  TWO launches: prep (fused histogram/append)
// then the gemm.  Scan + scatter kernels eliminated.
// ---------------------------------------------------------------------------
extern "C" void kernel_launch(void* const* d_in, const int* in_sizes, int n_in,
                              void* d_out, int out_size) {
    const int*   pidx    = (const int*)  d_in[0];
    const float* pos     = (const float*)d_in[1];
    const float* xs      = (const float*)d_in[2];
    const float* kernels = (const float*)d_in[3];
    const float* biases  = (const float*)d_in[4];
    float* out = (float*)d_out;
    (void)in_sizes; (void)n_in; (void)out_size;

    k_prep<<<(NPTS + 255) / 256, 256>>>(pidx, pos, out);
    k_cell_gemm<<<NGEMM, NTHR>>>(xs, kernels, biases, out);
}

// round 17
// speedup vs baseline: 4.0322x; 4.0322x over previous
#include <cuda_runtime.h>
#include <stdint.h>

// Problem constants (fixed by the dataset)
#define NPTS      32768
#define NKERN     4
#define GRID      16
#define C_IN      64
#define C_OUT     64
#define NCELLS    (NKERN * GRID * GRID * GRID)   // 16384
#define NENT      (NPTS * 8)                     // 262144
#define CPC       8                              // cells per CTA
#define NGEMM     (NCELLS / CPC)                 // 2048 CTAs
#define B         32                             // batch (slots)
#define YROW      68                             // floats per y row (272B, 16B-aligned)
#define NTHR      128                            // 4 warps

// ---------------------------------------------------------------------------
// Device scratch (static __device__ globals; no cudaMalloc anywhere).
// g_counts zero at load; re-zeroed in k_scatter.  g_sorted/g_swts padded +B
// (pad stays zero forever -> e=0 is a safe in-bounds dummy row).
// ---------------------------------------------------------------------------
__device__ __align__(16) unsigned g_counts[NCELLS];
__device__ __align__(16) unsigned g_offsets[NCELLS + 4];   // +4: uint4 tail room
__device__ __align__(16) unsigned g_cursor[NCELLS];
__device__ unsigned g_cells[NENT];
__device__ float    g_wts[NENT];
__device__ unsigned g_sorted[NENT + B];
__device__ float    g_swts[NENT + B];

// ---------------------------------------------------------------------------
// asm helpers
// ---------------------------------------------------------------------------
__device__ __forceinline__ void ffma2(unsigned long long& d,
                                      unsigned long long a,
                                      unsigned long long b) {
    asm("fma.rn.f32x2 %0, %1, %2, %0;" : "+l"(d) : "l"(a), "l"(b));
}
__device__ __forceinline__ unsigned long long bcast2(float v) {
    unsigned long long r;
    asm("mov.b64 %0, {%1, %1};" : "=l"(r) : "f"(v));
    return r;
}
__device__ __forceinline__ float2 unpack2(unsigned long long v) {
    float2 r;
    asm("mov.b64 {%0, %1}, %2;" : "=f"(r.x), "=f"(r.y) : "l"(v));
    return r;
}
__device__ __forceinline__ uint32_t smem_u32(const void* p) {
    uint32_t a;
    asm("{ .reg .u64 t; cvta.to.shared.u64 t, %1; cvt.u32.u64 %0, t; }"
        : "=r"(a) : "l"(p));
    return a;
}
__device__ __forceinline__ void mbar_init(uint32_t mbar, unsigned count) {
    asm volatile("mbarrier.init.shared.b64 [%0], %1;" :: "r"(mbar), "r"(count) : "memory");
}
__device__ __forceinline__ void mbar_expect_tx(uint32_t mbar, unsigned bytes) {
    asm volatile("mbarrier.arrive.expect_tx.shared.b64 _, [%0], %1;"
                 :: "r"(mbar), "r"(bytes) : "memory");
}
__device__ __forceinline__ void mbar_wait(uint32_t mbar, unsigned parity) {
    asm volatile(
        "{\n\t.reg .pred P;\n"
        "W%=:\n\t"
        "mbarrier.try_wait.parity.shared::cta.b64 P, [%0], %1, 0x989680;\n\t"
        "@P bra D%=;\n\t"
        "bra W%=;\n"
        "D%=:\n\t}"
        :: "r"(mbar), "r"(parity) : "memory");
}
__device__ __forceinline__ void bulk_g2s(uint32_t dst, const void* src,
                                         unsigned bytes, uint32_t mbar) {
    asm volatile(
        "cp.async.bulk.shared::cta.global.mbarrier::complete_tx::bytes "
        "[%0], [%1], %2, [%3];"
        :: "r"(dst), "l"(src), "r"(bytes), "r"(mbar) : "memory");
}
__device__ __forceinline__ void red_add_v4(float* gptr, float4 v) {
    asm volatile("red.global.add.v4.f32 [%0], {%1, %2, %3, %4};"
                 :: "l"(gptr), "f"(v.x), "f"(v.y), "f"(v.z), "f"(v.w)
                 : "memory");
}
__device__ __forceinline__ void cp_async16(uint32_t dst, const void* src) {
    asm volatile("cp.async.cg.shared.global [%0], [%1], 16;"
                 :: "r"(dst), "l"(src) : "memory");
}
__device__ __forceinline__ void cp_async4(uint32_t dst, const void* src) {
    asm volatile("cp.async.ca.shared.global [%0], [%1], 4;"
                 :: "r"(dst), "l"(src) : "memory");
}
__device__ __forceinline__ void cp_commit() {
    asm volatile("cp.async.commit_group;" ::: "memory");
}
__device__ __forceinline__ void cp_wait1() {
    asm volatile("cp.async.wait_group 1;" ::: "memory");
}

// ---------------------------------------------------------------------------
// K1: zero d_out + per-point corners/weights + cell histogram
// ---------------------------------------------------------------------------
__global__ void k_prep(const int* __restrict__ pidx,
                       const float* __restrict__ pos,
                       float* __restrict__ out) {
    int n = blockIdx.x * blockDim.x + threadIdx.x;

    float4 z = make_float4(0.f, 0.f, 0.f, 0.f);
    #pragma unroll
    for (int i = n; i < NPTS * (C_OUT / 4); i += NPTS)
        ((float4*)out)[i] = z;

    if (n >= NPTS) return;

    float lx = pos[n * 3 + 0] * (float)GRID - 0.5f;
    float ly = pos[n * 3 + 1] * (float)GRID - 0.5f;
    float lz = pos[n * 3 + 2] * (float)GRID - 0.5f;
    float fx = floorf(lx), fy = floorf(ly), fz = floorf(lz);
    float cwx = lx - fx, cwy = ly - fy, cwz = lz - fz;
    float fwx = 1.f - cwx, fwy = 1.f - cwy, fwz = 1.f - cwz;
    int ix = (int)fx, iy = (int)fy, iz = (int)fz;
    int pi = pidx[n];

    #pragma unroll
    for (int k = 0; k < 8; k++) {
        int bx = k & 1, by = (k >> 1) & 1, bz = (k >> 2) & 1;
        int jx = min(max(ix + bx, 0), GRID - 1);
        int jy = min(max(iy + by, 0), GRID - 1);
        int jz = min(max(iz + bz, 0), GRID - 1);
        float w = (bx ? cwx : fwx) * (by ? cwy : fwy) * (bz ? cwz : fwz);
        unsigned cell = (((unsigned)pi * GRID + jz) * GRID + jy) * GRID + jx;
        g_cells[n * 8 + k] = cell;
        g_wts[n * 8 + k] = w;
        atomicAdd(&g_counts[cell], 1u);
    }
}

// ---------------------------------------------------------------------------
// K2: single-block exclusive scan of 16384 counts.
//     1024 threads x 16 elements, ALL global traffic via uint4 (coalesced
//     LDG.128/STG.128 -- the old 512x32 scalar version had 32-way
//     uncoalesced per-thread-contiguous loads).
// ---------------------------------------------------------------------------
__global__ __launch_bounds__(1024) void k_scan() {
    __shared__ unsigned part[1024];
    int t = threadIdx.x;

    // load 16 counts as 4 x uint4 (coalesced)
    uint4 c4[4];
    #pragma unroll
    for (int q = 0; q < 4; q++)
        c4[q] = ((const uint4*)g_counts)[t * 4 + q];
    unsigned c[16];
    #pragma unroll
    for (int q = 0; q < 4; q++) {
        c[q * 4 + 0] = c4[q].x; c[q * 4 + 1] = c4[q].y;
        c[q * 4 + 2] = c4[q].z; c[q * 4 + 3] = c4[q].w;
    }
    unsigned sum = 0;
    #pragma unroll
    for (int i = 0; i < 16; i++) sum += c[i];
    part[t] = sum;
    __syncthreads();

    // Hillis-Steele inclusive scan over 1024 partials (10 rounds)
    for (int off = 1; off < 1024; off <<= 1) {
        unsigned v = 0;
        if (t >= off) v = part[t - off];
        __syncthreads();
        if (t >= off) part[t] += v;
        __syncthreads();
    }

    unsigned run = (t == 0) ? 0u : part[t - 1];
    unsigned o[16];
    #pragma unroll
    for (int i = 0; i < 16; i++) { o[i] = run; run += c[i]; }

    #pragma unroll
    for (int q = 0; q < 4; q++) {
        uint4 v = make_uint4(o[q * 4 + 0], o[q * 4 + 1], o[q * 4 + 2], o[q * 4 + 3]);
        ((uint4*)g_offsets)[t * 4 + q] = v;
        ((uint4*)g_cursor)[t * 4 + q] = v;
    }
    if (t == 1023) g_offsets[NCELLS] = run;   // == NENT
}

// ---------------------------------------------------------------------------
// K3: scatter entries into cell-grouped order (+ sorted weights, counts reset)
// ---------------------------------------------------------------------------
__global__ void k_scatter() {
    int e = blockIdx.x * blockDim.x + threadIdx.x;
    if (e < NCELLS) g_counts[e] = 0u;
    if (e >= NENT) return;
    unsigned cell = g_cells[e];
    unsigned slot = atomicAdd(&g_cursor[cell], 1u);
    g_sorted[slot] = (unsigned)e;
    g_swts[slot] = g_wts[e];
}

// ---------------------------------------------------------------------------
// K4: pipelined per-cell GEMM (the proven 141.8us kernel, unchanged).
//   - 128 thr, B=32.  fj = t&15 (16 col groups of 4), ei = t>>4 (8 slot
//     groups of 4).  Thread tile: 4 slots x 4 cols (0.125 LDS.128/MAC).
//   - Warp w covers slots [8w, 8w+8): whole-warp padding skip.
//   - y staged as raw xs rows via cp.async one batch ahead (w in epilogue);
//     e/w staged three batches ahead; wait_group 1.
//   - K (16KB)+bias double-buffered via cp.async.bulk + mbarrier.
//   - Epilogue: red.global.add.v4.f32 straight into d_out.
// ---------------------------------------------------------------------------
#define KBYTES   (C_IN * C_OUT * 4)          // 16384
#define BBYTES   (C_OUT * 4)                 // 256
#define TXBYTES  (KBYTES + BBYTES)           // 16640

#define ADV(ci, bs) do { (bs) += B;                                           \
    while ((ci) < CPC && (bs) >= (int)(soff[(ci)+1] - soff[(ci)])) {          \
        (ci)++; (bs) = 0; } } while (0)

__global__ __launch_bounds__(NTHR) void k_cell_gemm(
    const float* __restrict__ xs,
    const float* __restrict__ kernels,
    const float* __restrict__ biases,
    float* __restrict__ out) {

    __shared__ __align__(16) float ksm[2][C_IN * C_OUT];   // 32KB
    __shared__ __align__(16) float bsm[2][C_OUT];          // 512B
    __shared__ __align__(16) float ybuf[2][B][YROW];       // 17.4KB
    __shared__ unsigned ebuf[4][B];                        // 512B
    __shared__ float    wbuf[4][B];                        // 512B
    __shared__ unsigned soff[CPC + 1];
    __shared__ __align__(8) unsigned long long mbar_s[2];

    const int t  = threadIdx.x;      // 0..127
    const int fj = t & 15;           // 16 col groups of 4
    const int ei = t >> 4;           // 8 slot groups of 4
    const int yb = ei * 4;           // first of this thread's 4 slots
    const int kb = fj * 4;           // first of this thread's 4 columns
    const int cell0 = blockIdx.x * CPC;

    uint32_t mb0 = smem_u32(&mbar_s[0]);
    uint32_t mb1 = smem_u32(&mbar_s[1]);
    uint32_t kd0 = smem_u32(&ksm[0][0]);
    uint32_t kd1 = smem_u32(&ksm[1][0]);
    uint32_t bd0 = smem_u32(&bsm[0][0]);
    uint32_t bd1 = smem_u32(&bsm[1][0]);

    if (t <= CPC) soff[t] = g_offsets[cell0 + t];
    if (t == 0) { mbar_init(mb0, 1); mbar_init(mb1, 1); }
    __syncthreads();

    // compute cursor (batch b)
    int cci = 0, cbase = 0;
    while (cci < CPC && (int)(soff[cci + 1] - soff[cci]) == 0) cci++;
    if (cci == CPC) return;   // empty CTA

    // prologue: K for first nonempty cell into buf0
    if (t == 0) {
        mbar_expect_tx(mb0, TXBYTES);
        bulk_g2s(kd0, kernels + (size_t)(cell0 + cci) * (C_IN * C_OUT), KBYTES, mb0);
        bulk_g2s(bd0, biases  + (size_t)(cell0 + cci) * C_OUT,          BBYTES, mb0);
    }

    // cursor copies for batches 1..4
    int c1i = cci, c1b = cbase; ADV(c1i, c1b);
    int c2i = c1i, c2b = c1b;   ADV(c2i, c2b);
    int c3i = c2i, c3b = c2b;   ADV(c3i, c3b);
    int c4i = c3i, c4b = c3b;   ADV(c4i, c4b);

    // sync-load e/w for batches 0 and 1
    if (t < B) {
        int s0 = (int)soff[cci] + cbase;
        ebuf[0][t] = g_sorted[s0 + t];
        wbuf[0][t] = g_swts[s0 + t];
        if (c1i < CPC) {
            int s1 = (int)soff[c1i] + c1b;
            ebuf[1][t] = g_sorted[s1 + t];
            wbuf[1][t] = g_swts[s1 + t];
        }
    }
    __syncthreads();

    // group A: y[0] (from ebuf[0]) + e[2]   (512 x 16B over 128 threads)
    {
        #pragma unroll
        for (int k = 0; k < 4; k++) {
            int idx = t + k * NTHR, row = idx >> 4, ch = idx & 15;
            unsigned e = ebuf[0][row];
            cp_async16(smem_u32(&ybuf[0][row][0]) + ch * 16,
                       xs + (size_t)(e >> 3) * C_IN + ch * 4);
        }
        if (c2i < CPC) {
            int s2 = (int)soff[c2i] + c2b;
            if (t < B)            cp_async4(smem_u32(&ebuf[2][t]),     g_sorted + s2 + t);
            else if (t < 2 * B)   cp_async4(smem_u32(&wbuf[2][t - B]), g_swts   + s2 + (t - B));
        }
        cp_commit();
    }
    // group B: y[1] (from ebuf[1]) + e[3]
    {
        if (c1i < CPC) {
            #pragma unroll
            for (int k = 0; k < 4; k++) {
                int idx = t + k * NTHR, row = idx >> 4, ch = idx & 15;
                unsigned e = ebuf[1][row];
                cp_async16(smem_u32(&ybuf[1][row][0]) + ch * 16,
                           xs + (size_t)(e >> 3) * C_IN + ch * 4);
            }
        }
        if (c3i < CPC) {
            int s3 = (int)soff[c3i] + c3b;
            if (t < B)            cp_async4(smem_u32(&ebuf[3][t]),     g_sorted + s3 + t);
            else if (t < 2 * B)   cp_async4(smem_u32(&wbuf[3][t - B]), g_swts   + s3 + (t - B));
        }
        cp_commit();
    }
    cp_wait1();        // group A complete: y[0], e[2]
    __syncthreads();

    unsigned kpar0 = 0, kpar1 = 0;
    int kq = -1, prev_ci = -1;
    int b = 0;
    int ici = c2i, icb = c2b;   // issue cursor (batch b+2)
    int eci = c4i, ecb = c4b;   // e cursor (batch b+4)

    while (cci < CPC) {
        int nent = (int)(soff[cci + 1] - soff[cci]);
        int nb = min(B, nent - cbase);
        bool newcell = (cci != prev_ci);
        prev_ci = cci;

        if (newcell) {
            kq++;
            if (t == 0) {
                int nc = cci + 1;
                while (nc < CPC && soff[nc + 1] == soff[nc]) nc++;
                if (nc < CPC) {
                    int nbuf = (kq + 1) & 1;
                    uint32_t mb = nbuf ? mb1 : mb0;
                    mbar_expect_tx(mb, TXBYTES);
                    bulk_g2s(nbuf ? kd1 : kd0,
                             kernels + (size_t)(cell0 + nc) * (C_IN * C_OUT), KBYTES, mb);
                    bulk_g2s(nbuf ? bd1 : bd0,
                             biases + (size_t)(cell0 + nc) * C_OUT, BBYTES, mb);
                }
            }
            if (kq & 1) { mbar_wait(mb1, kpar1); kpar1 ^= 1u; }
            else        { mbar_wait(mb0, kpar0); kpar0 ^= 1u; }
        }

        const int kbuf = kq & 1;
        const int ysel = b & 1;
        const int ring = b & 3;

        // ---- compute batch b (warps whose 8 slots are all padding skip) ----
        if (yb < nb) {
            const float* kcur = ksm[kbuf];
            const float* bcur = bsm[kbuf];
            const float* y0p = &ybuf[ysel][yb + 0][0];
            const float* y1p = &ybuf[ysel][yb + 1][0];
            const float* y2p = &ybuf[ysel][yb + 2][0];
            const float* y3p = &ybuf[ysel][yb + 3][0];
            unsigned long long a0[2] = {0, 0}, a1[2] = {0, 0};
            unsigned long long a2[2] = {0, 0}, a3[2] = {0, 0};

            #pragma unroll
            for (int cb = 0; cb < 16; cb++) {
                float4 ya = *(const float4*)(y0p + cb * 4);
                float4 ybv = *(const float4*)(y1p + cb * 4);
                float4 yc = *(const float4*)(y2p + cb * 4);
                float4 yd = *(const float4*)(y3p + cb * 4);
                const float* kp = kcur + cb * 4 * C_OUT + kb;
                ulonglong2 k0 = *(const ulonglong2*)(kp);
                ulonglong2 k1 = *(const ulonglong2*)(kp + C_OUT);
                ulonglong2 k2 = *(const ulonglong2*)(kp + 2 * C_OUT);
                ulonglong2 k3 = *(const ulonglong2*)(kp + 3 * C_OUT);
                unsigned long long u;
                u = bcast2(ya.x);  ffma2(a0[0], u, k0.x); ffma2(a0[1], u, k0.y);
                u = bcast2(ya.y);  ffma2(a0[0], u, k1.x); ffma2(a0[1], u, k1.y);
                u = bcast2(ya.z);  ffma2(a0[0], u, k2.x); ffma2(a0[1], u, k2.y);
                u = bcast2(ya.w);  ffma2(a0[0], u, k3.x); ffma2(a0[1], u, k3.y);
                u = bcast2(ybv.x); ffma2(a1[0], u, k0.x); ffma2(a1[1], u, k0.y);
                u = bcast2(ybv.y); ffma2(a1[0], u, k1.x); ffma2(a1[1], u, k1.y);
                u = bcast2(ybv.z); ffma2(a1[0], u, k2.x); ffma2(a1[1], u, k2.y);
                u = bcast2(ybv.w); ffma2(a1[0], u, k3.x); ffma2(a1[1], u, k3.y);
                u = bcast2(yc.x);  ffma2(a2[0], u, k0.x); ffma2(a2[1], u, k0.y);
                u = bcast2(yc.y);  ffma2(a2[0], u, k1.x); ffma2(a2[1], u, k1.y);
                u = bcast2(yc.z);  ffma2(a2[0], u, k2.x); ffma2(a2[1], u, k2.y);
                u = bcast2(yc.w);  ffma2(a2[0], u, k3.x); ffma2(a2[1], u, k3.y);
                u = bcast2(yd.x);  ffma2(a3[0], u, k0.x); ffma2(a3[1], u, k0.y);
                u = bcast2(yd.y);  ffma2(a3[0], u, k1.x); ffma2(a3[1], u, k1.y);
                u = bcast2(yd.z);  ffma2(a3[0], u, k2.x); ffma2(a3[1], u, k2.y);
                u = bcast2(yd.w);  ffma2(a3[0], u, k3.x); ffma2(a3[1], u, k3.y);
            }

            float bx = bcur[kb],     by = bcur[kb + 1];
            float bz = bcur[kb + 2], bw = bcur[kb + 3];
            unsigned long long* accs[4] = {a0, a1, a2, a3};
            #pragma unroll
            for (int j = 0; j < 4; j++) {
                int slot = yb + j;
                if (slot < nb) {
                    unsigned e = ebuf[ring][slot];
                    float wt = wbuf[ring][slot];
                    float2 lo = unpack2(accs[j][0]);
                    float2 hi = unpack2(accs[j][1]);
                    float4 o = make_float4(wt * (lo.x + bx), wt * (lo.y + by),
                                           wt * (hi.x + bz), wt * (hi.y + bw));
                    red_add_v4(out + (size_t)(e >> 3) * C_OUT + kb, o);
                }
            }
        }
        __syncthreads();   // everyone done with ybuf[ysel], ebuf[ring]

        // ---- issue group b+2: y[b+2] into ybuf[ysel], e[b+4] into ring ----
        if (ici < CPC) {
            int iring = (b + 2) & 3;
            #pragma unroll
            for (int k = 0; k < 4; k++) {
                int idx = t + k * NTHR, row = idx >> 4, ch = idx & 15;
                unsigned e = ebuf[iring][row];
                cp_async16(smem_u32(&ybuf[ysel][row][0]) + ch * 16,
                           xs + (size_t)(e >> 3) * C_IN + ch * 4);
            }
        }
        if (eci < CPC) {
            int ering = (b + 4) & 3;   // == ring; e[b] is dead now
            int es = (int)soff[eci] + ecb;
            if (t < B)          cp_async4(smem_u32(&ebuf[ering][t]),     g_sorted + es + t);
            else if (t < 2 * B) cp_async4(smem_u32(&wbuf[ering][t - B]), g_swts   + es + (t - B));
        }
        cp_commit();
        cp_wait1();        // group b+1 complete: y[b+1], e[b+3]
        __syncthreads();

        ADV(cci, cbase);
        ADV(ici, icb);
        ADV(eci, ecb);
        b++;
    }
}

// ---------------------------------------------------------------------------
// Launcher (graph-capturable).  4 launches; gemm 4th (ncu capture slot).
// ---------------------------------------------------------------------------
extern "C" void kernel_launch(void* const* d_in, const int* in_sizes, int n_in,
                              void* d_out, int out_size) {
    const int*   pidx    = (const int*)  d_in[0];
    const float* pos     = (const float*)d_in[1];
    const float* xs      = (const float*)d_in[2];
    const float* kernels = (const float*)d_in[3];
    const float* biases  = (const float*)d_in[4];
    float* out = (float*)d_out;
    (void)in_sizes; (void)n_in; (void)out_size;

    k_prep<<<(NPTS + 255) / 256, 256>>>(pidx, pos, out);
    k_scan<<<1, 1024>>>();
    k_scatter<<<(NENT + 255) / 256, 256>>>();
    k_cell_gemm<<<NGEMM, NTHR>>>(xs, kernels, biases, out);
}